// round 6
// baseline (speedup 1.0000x reference)
#include <cuda_runtime.h>
#include <cuda_bf16.h>
#include <cuda_fp16.h>
#include <math.h>
#include <stdint.h>

#define B_    64
#define D_    512
#define S_    2048
#define K_    8
#define NCAND 16
#define TWO_D 1024

// ---------------- scratch (static device globals) ----------------
__device__ __nv_bfloat16 g_pehi[S_ * TWO_D];   // PE hi [s][e] (4 MB)
__device__ __nv_bfloat16 g_pelo[S_ * TWO_D];   // PE lo [s][e] (4 MB)
__device__ __nv_bfloat16 g_w1h [D_ * TWO_D];   // W1 hi [d][e] full
__device__ __nv_bfloat16 g_w1lo[D_ * TWO_D];   // W1 lo [d][e] full
__device__ __half        g_w1f [D_ * D_];      // W1[:, :512] fp16 [d][e]
__device__ float g_w1t [D_ * D_];              // W1[:, :512] fp32 [e][d]
__device__ float g_p1  [S_ * D_];              // PE@W1^T + b1 [s][d]
__device__ float g_mpart[(S_ / 64) * B_ * D_]; // mean partials [tile][b*D+d]
__device__ float g_gb  [B_ * D_];
__device__ float g_score[B_ * S_];
__device__ int   g_cand[B_ * NCAND];
__device__ float g_cs  [B_ * 2 * NCAND];
__device__ int   g_idx [B_ * K_];

// ---------------- PTX helpers ----------------
__device__ __forceinline__ uint32_t smem_u32(const void* p) {
    return (uint32_t)__cvta_generic_to_shared(p);
}
__device__ __forceinline__ uint32_t h2u(__half2 h) {
    union { __half2 h; uint32_t u; } cvt;
    cvt.h = h;
    return cvt.u;
}
__device__ __forceinline__ void cp16(uint32_t dst, const void* src) {
    asm volatile("cp.async.cg.shared.global [%0], [%1], 16;" :: "r"(dst), "l"(src));
}
#define CP_COMMIT() asm volatile("cp.async.commit_group;" ::: "memory")
#define CP_WAIT(n)  asm volatile("cp.async.wait_group %0;" :: "n"(n) : "memory")

__device__ __forceinline__ void ldsm4(uint32_t* r, uint32_t a) {
    asm volatile("ldmatrix.sync.aligned.m8n8.x4.shared.b16 {%0,%1,%2,%3}, [%4];"
        : "=r"(r[0]), "=r"(r[1]), "=r"(r[2]), "=r"(r[3]) : "r"(a));
}
__device__ __forceinline__ void ldsm4t(uint32_t* r, uint32_t a) {
    asm volatile("ldmatrix.sync.aligned.m8n8.x4.trans.shared.b16 {%0,%1,%2,%3}, [%4];"
        : "=r"(r[0]), "=r"(r[1]), "=r"(r[2]), "=r"(r[3]) : "r"(a));
}
__device__ __forceinline__ void ldsm2(uint32_t* r, uint32_t a) {
    asm volatile("ldmatrix.sync.aligned.m8n8.x2.shared.b16 {%0,%1}, [%2];"
        : "=r"(r[0]), "=r"(r[1]) : "r"(a));
}
// bf16 inputs, fp32 accum (exact p1 path)
__device__ __forceinline__ void mma_bf_f32(float* c, const uint32_t* a, const uint32_t* b) {
    asm volatile(
        "mma.sync.aligned.m16n8k16.row.col.f32.bf16.bf16.f32 "
        "{%0,%1,%2,%3}, {%4,%5,%6,%7}, {%8,%9}, {%0,%1,%2,%3};"
        : "+f"(c[0]), "+f"(c[1]), "+f"(c[2]), "+f"(c[3])
        : "r"(a[0]), "r"(a[1]), "r"(a[2]), "r"(a[3]), "r"(b[0]), "r"(b[1]));
}
// fp16 inputs, fp16 accum (fast approx path)
__device__ __forceinline__ void mma_h_h(uint32_t* c, const uint32_t* a, const uint32_t* b) {
    asm volatile(
        "mma.sync.aligned.m16n8k16.row.col.f16.f16.f16.f16 "
        "{%0,%1}, {%2,%3,%4,%5}, {%6,%7}, {%0,%1};"
        : "+r"(c[0]), "+r"(c[1])
        : "r"(a[0]), "r"(a[1]), "r"(a[2]), "r"(a[3]), "r"(b[0]), "r"(b[1]));
}

// ---------------------------------------------------------------
// 1) transpose (64x64, float4): x[b][d][s] -> out_feat[b][s][d]
//    + mean partials via in-register shfl reduction
// ---------------------------------------------------------------
__global__ void transpose_fused_kernel(const float* __restrict__ x,
                                       float* __restrict__ out_feat) {
    __shared__ float tile[64][65];
    int b  = blockIdx.z;
    int d0 = blockIdx.y * 64;
    int s0 = blockIdx.x * 64;
    int tid = threadIdx.x;
    int tx = tid & 15, ty = tid >> 4;
    int lane = tid & 31;
    const float* xb = x + (size_t)b * D_ * S_ + s0 + tx * 4;
    #pragma unroll
    for (int r = 0; r < 4; r++) {
        int d = ty + r * 16;
        float4 v = *(const float4*)(xb + (size_t)(d0 + d) * S_);
        tile[d][tx * 4 + 0] = v.x; tile[d][tx * 4 + 1] = v.y;
        tile[d][tx * 4 + 2] = v.z; tile[d][tx * 4 + 3] = v.w;
        float ps = (v.x + v.y) + (v.z + v.w);
        #pragma unroll
        for (int o = 8; o > 0; o >>= 1)
            ps += __shfl_down_sync(0xffffffffu, ps, o, 16);
        if ((lane & 15) == 0)
            g_mpart[(size_t)blockIdx.x * (B_ * D_) + b * D_ + d0 + d] = ps;
    }
    __syncthreads();
    float* ob = out_feat + (size_t)b * S_ * D_ + d0 + tx * 4;
    #pragma unroll
    for (int r = 0; r < 4; r++) {
        int s = ty + r * 16;
        float4 v = make_float4(tile[tx * 4 + 0][s], tile[tx * 4 + 1][s],
                               tile[tx * 4 + 2][s], tile[tx * 4 + 3][s]);
        *(float4*)(ob + (size_t)(s0 + s) * D_) = v;
    }
}

// ---------------------------------------------------------------
// 2) merged PE (hi/lo bf16) + W1 conversions + mean/g epilogue
//    blocks [0,S): PE rows; [S, S+1024): W1; [S+1024, S+1024+64): g
// ---------------------------------------------------------------
__global__ void pew1_meang_kernel(const float* __restrict__ W1) {
    __shared__ float sm[D_];
    int bx = blockIdx.x;
    if (bx < S_) {
        int s = bx, i = threadIdx.x;  // i = 0..511, e = 2i, 2i+1
        float div = expf(-(float)(2 * i) * (logf(10000.0f) / (float)TWO_D));
        float sv, cv;
        sincosf((float)s * div, &sv, &cv);
        __nv_bfloat16 hs = __float2bfloat16_rn(sv);
        __nv_bfloat16 hc = __float2bfloat16_rn(cv);
        __nv_bfloat16 ls = __float2bfloat16_rn(sv - __bfloat162float(hs));
        __nv_bfloat16 lc = __float2bfloat16_rn(cv - __bfloat162float(hc));
        ((__nv_bfloat162*)g_pehi)[(size_t)s * (TWO_D / 2) + i] =
            __nv_bfloat162(hs, hc);
        ((__nv_bfloat162*)g_pelo)[(size_t)s * (TWO_D / 2) + i] =
            __nv_bfloat162(ls, lc);
    } else if (bx < S_ + (D_ * TWO_D) / 512) {
        int idx = (bx - S_) * 512 + threadIdx.x;    // d*1024 + e
        int d = idx >> 10, e = idx & 1023;
        float v = W1[idx];
        __nv_bfloat16 h = __float2bfloat16_rn(v);
        g_w1h[idx]  = h;
        g_w1lo[idx] = __float2bfloat16_rn(v - __bfloat162float(h));
        if (e < 512) {
            g_w1f[d * 512 + e] = __float2half_rn(v);
            g_w1t[(size_t)e * D_ + d] = v;
        }
    } else {
        int b = bx - S_ - (D_ * TWO_D) / 512;
        int d = threadIdx.x;  // 512 threads
        float s = 0.f;
        #pragma unroll
        for (int t = 0; t < S_ / 64; t++)
            s += g_mpart[(size_t)t * (B_ * D_) + b * D_ + d];
        sm[d] = s * (1.0f / S_);
        __syncthreads();
        const float4* w = (const float4*)(W1 + (size_t)d * TWO_D + D_);
        float acc = 0.f;
        #pragma unroll 8
        for (int e4 = 0; e4 < D_ / 4; e4++) {
            float4 v = w[e4];
            acc = fmaf(sm[4 * e4 + 0], v.x, acc);
            acc = fmaf(sm[4 * e4 + 1], v.y, acc);
            acc = fmaf(sm[4 * e4 + 2], v.z, acc);
            acc = fmaf(sm[4 * e4 + 3], v.w, acc);
        }
        g_gb[b * D_ + d] = acc;
    }
}

// ---------------------------------------------------------------
// 3) p1 via hi/lo bf16 MMA (3 products, fp32 accum): effectively exact.
// ---------------------------------------------------------------
#define P1_SMEM (2 * 65536)

__global__ void __launch_bounds__(256, 1)
p1_mma_kernel(const float* __restrict__ b1) {
    extern __shared__ char dsm[];
    uint32_t smb = smem_u32(dsm);
    int tid = threadIdx.x, lane = tid & 31, w = tid >> 5;
    int wm = w & 3, wn = w >> 2;
    int quad = lane >> 2, qd = lane & 3;
    int s0 = blockIdx.x * 128;
    int d0b = blockIdx.y * 128;

    const char* Ah = (const char*)g_pehi + (size_t)s0 * 2048;
    const char* Al = (const char*)g_pelo + (size_t)s0 * 2048;
    const char* Bh = (const char*)g_w1h + (size_t)d0b * 2048;
    const char* Bl = (const char*)g_w1lo + (size_t)d0b * 2048;

    #define P1_PF(t) do { \
        int p_ = (t) & 1; \
        uint32_t base_ = smb + p_ * 65536; \
        _Pragma("unroll") \
        for (int q = 0; q < 4; q++) { \
            int idx = tid + q * 256; \
            int row = idx >> 3, c = idx & 7; \
            uint32_t off = row * 128 + (((c ^ (row & 7))) << 4); \
            size_t src = (size_t)row * 2048 + (size_t)(t) * 128 + c * 16; \
            cp16(base_ + off,          Ah + src); \
            cp16(base_ + 16384 + off,  Al + src); \
            cp16(base_ + 32768 + off,  Bh + src); \
            cp16(base_ + 49152 + off,  Bl + src); \
        } \
        CP_COMMIT(); \
    } while (0)

    P1_PF(0);
    P1_PF(1);

    float C[2][8][4];
    #pragma unroll
    for (int i = 0; i < 2; i++)
        #pragma unroll
        for (int j = 0; j < 8; j++)
            #pragma unroll
            for (int k = 0; k < 4; k++) C[i][j][k] = 0.f;

    for (int t = 0; t < 16; ++t) {
        if (t >= 14) { CP_WAIT(0); } else { CP_WAIT(1); }
        __syncthreads();
        uint32_t bA = smb + (t & 1) * 65536;
        #pragma unroll
        for (int kk = 0; kk < 4; kk++) {
            uint32_t ah[2][4], al[2][4];
            #pragma unroll
            for (int i = 0; i < 2; i++) {
                int r = wm * 32 + i * 16 + (lane & 15);
                uint32_t ch = (uint32_t)((kk << 1) | (lane >> 4));
                uint32_t off = r * 128 + ((ch ^ (uint32_t)(r & 7)) << 4);
                ldsm4(ah[i], bA + off);
                ldsm4(al[i], bA + 16384 + off);
            }
            uint32_t bh[8][2], bl[8][2];
            #pragma unroll
            for (int j = 0; j < 8; j++) {
                int rn = wn * 64 + j * 8 + (lane & 7);
                uint32_t ch = (uint32_t)((kk << 1) | ((lane >> 3) & 1));
                uint32_t off = rn * 128 + ((ch ^ (uint32_t)(rn & 7)) << 4);
                ldsm2(bh[j], bA + 32768 + off);
                ldsm2(bl[j], bA + 49152 + off);
            }
            #pragma unroll
            for (int i = 0; i < 2; i++)
                #pragma unroll
                for (int j = 0; j < 8; j++) {
                    mma_bf_f32(C[i][j], ah[i], bh[j]);
                    mma_bf_f32(C[i][j], ah[i], bl[j]);
                    mma_bf_f32(C[i][j], al[i], bh[j]);
                }
        }
        __syncthreads();
        if (t + 2 < 16) P1_PF(t + 2);
    }

    #pragma unroll
    for (int i = 0; i < 2; i++) {
        int sg = s0 + wm * 32 + i * 16 + quad;
        #pragma unroll
        for (int j = 0; j < 8; j++) {
            int d = d0b + wn * 64 + j * 8 + qd * 2;
            float2 bv = *(const float2*)(b1 + d);
            *(float2*)(g_p1 + (size_t)sg * D_ + d) =
                make_float2(C[i][j][0] + bv.x, C[i][j][1] + bv.y);
            *(float2*)(g_p1 + (size_t)(sg + 8) * D_ + d) =
                make_float2(C[i][j][2] + bv.x, C[i][j][3] + bv.y);
        }
    }
    #undef P1_PF
}

// ---------------------------------------------------------------
// 4) MAIN: fp16 mma GEMM (f16 accum) + fused relu/W2 epilogue.
// ---------------------------------------------------------------
#define SMEM_A   (8 * 16384)        // 128 KB: 8 chunks of [64e][128s] fp16
#define SMEM_B   (2 * 16384)
#define SMEM_DYN (SMEM_A + SMEM_B)  // 160 KB

__global__ void __launch_bounds__(256, 1)
fused_mma_kernel(const float* __restrict__ x, const float* __restrict__ W2,
                 const float* __restrict__ b2)
{
    extern __shared__ char dsm[];
    __shared__ float sW2[D_];
    __shared__ float sG[D_];
    __shared__ float sred[2][128];

    const uint32_t smA = smem_u32(dsm);
    const uint32_t smB = smA + SMEM_A;

    int tid = threadIdx.x;
    int lane = tid & 31;
    int w = tid >> 5;
    int wm = w & 3, wn = w >> 2;
    int quad = lane >> 2, qd = lane & 3;
    int b = blockIdx.y;
    int s0 = blockIdx.x * 128;

    for (int i = tid; i < D_; i += 256) {
        sW2[i] = W2[i];
        sG[i]  = g_gb[b * D_ + i];
    }

    const float* xA = x + (size_t)b * D_ * S_ + s0;

    #define B_PF(tc) do { \
        const char* wB_ = (const char*)(g_w1f + (size_t)((tc) >> 3) * 128 * 512); \
        int kcn_ = (tc) & 7; \
        _Pragma("unroll") \
        for (int q = 0; q < 4; q++) { \
            int idx = tid + q * 256; \
            int row = idx >> 3, c = idx & 7; \
            uint32_t dst = smB + ((tc) & 1) * 16384 + row * 128 + (((c ^ (row & 7))) << 4); \
            cp16(dst, wB_ + row * 1024 + kcn_ * 128 + c * 16); \
        } \
        CP_COMMIT(); \
    } while (0)

    B_PF(0);
    B_PF(1);

    float4 st[8];
    #define A_LDG(kc) do { \
        _Pragma("unroll") \
        for (int q = 0; q < 8; q++) { \
            int idx = tid + q * 256; \
            int e = (kc) * 64 + (idx >> 5), c4 = idx & 31; \
            st[q] = __ldg((const float4*)(xA + (size_t)e * S_ + c4 * 4)); \
        } \
    } while (0)
    #define A_STS(kc) do { \
        _Pragma("unroll") \
        for (int q = 0; q < 8; q++) { \
            int idx = tid + q * 256; \
            int el = idx >> 5, c4 = idx & 31; \
            __half2 h01 = __floats2half2_rn(st[q].x, st[q].y); \
            __half2 h23 = __floats2half2_rn(st[q].z, st[q].w); \
            uint32_t off = (uint32_t)((kc) * 16384 + el * 256 + \
                (((c4 >> 1) ^ (el & 7)) << 4) + (c4 & 1) * 8); \
            *(uint2*)(dsm + off) = make_uint2(h2u(h01), h2u(h23)); \
        } \
    } while (0)

    A_LDG(0);

    uint32_t C[2][8][2];
    float acc[2][2] = {{0.f, 0.f}, {0.f, 0.f}};

    for (int t = 0; t < 32; ++t) {
        int kc = t & 7;
        int nb = t >> 3;
        if (kc == 0) {
            #pragma unroll
            for (int i = 0; i < 2; i++)
                #pragma unroll
                for (int j = 0; j < 8; j++) { C[i][j][0] = 0u; C[i][j][1] = 0u; }
        }
        if (t < 8) A_STS(t);
        if (t >= 30) { CP_WAIT(0); } else { CP_WAIT(1); }
        __syncthreads();
        if (t < 7) A_LDG(t + 1);

        uint32_t Abase = smA + kc * 16384;
        uint32_t Bbase = smB + (t & 1) * 16384;
        #pragma unroll
        for (int kk = 0; kk < 4; kk++) {
            uint32_t a[2][4];
            #pragma unroll
            for (int i = 0; i < 2; i++) {
                int s0m = wm * 32 + i * 16;
                int row = kk * 16 + ((lane >> 4) << 3) + (lane & 7);
                int col16 = (s0m >> 3) + ((lane >> 3) & 1);
                ldsm4t(a[i], Abase + row * 256 +
                             (((uint32_t)(col16 ^ (row & 7))) << 4));
            }
            uint32_t bf[8][2];
            #pragma unroll
            for (int j = 0; j < 8; j++) {
                int rn = wn * 64 + j * 8 + (lane & 7);
                uint32_t ch = (uint32_t)((kk << 1) | ((lane >> 3) & 1));
                ldsm2(bf[j], Bbase + rn * 128 + ((ch ^ (uint32_t)(rn & 7)) << 4));
            }
            #pragma unroll
            for (int i = 0; i < 2; i++)
                #pragma unroll
                for (int j = 0; j < 8; j++)
                    mma_h_h(C[i][j], a[i], bf[j]);
        }
        __syncthreads();
        if (t + 2 < 32) B_PF(t + 2);

        if (kc == 7) {
            int d0 = nb * 128;
            #pragma unroll
            for (int i = 0; i < 2; i++) {
                int r0 = wm * 32 + i * 16 + quad;
                #pragma unroll
                for (int j = 0; j < 8; j++) {
                    int d = d0 + wn * 64 + j * 8 + qd * 2;
                    float w2x = sW2[d], w2y = sW2[d + 1];
                    float gx = sG[d],  gy = sG[d + 1];
                    const float* p = g_p1 + (size_t)(s0 + r0) * D_ + d;
                    float2 pA = *(const float2*)p;
                    float2 pB = *(const float2*)(p + 8 * D_);
                    __half2 ha = *(__half2*)&C[i][j][0];
                    __half2 hb = *(__half2*)&C[i][j][1];
                    float v0 = fmaxf(__low2float(ha)  + pA.x + gx, 0.f);
                    float v1 = fmaxf(__high2float(ha) + pA.y + gy, 0.f);
                    float v2 = fmaxf(__low2float(hb)  + pB.x + gx, 0.f);
                    float v3 = fmaxf(__high2float(hb) + pB.y + gy, 0.f);
                    acc[i][0] = fmaf(v0, w2x, fmaf(v1, w2y, acc[i][0]));
                    acc[i][1] = fmaf(v2, w2x, fmaf(v3, w2y, acc[i][1]));
                }
            }
        }
    }
    #undef B_PF
    #undef A_LDG
    #undef A_STS

    #pragma unroll
    for (int i = 0; i < 2; i++)
        #pragma unroll
        for (int m = 0; m < 2; m++) {
            float v = acc[i][m];
            v += __shfl_xor_sync(0xffffffffu, v, 1);
            v += __shfl_xor_sync(0xffffffffu, v, 2);
            if (qd == 0) sred[wn][wm * 32 + i * 16 + m * 8 + quad] = v;
        }
    __syncthreads();
    if (tid < 128)
        g_score[(size_t)b * S_ + s0 + tid] = sred[0][tid] + sred[1][tid] + b2[0];
}

// ---------------------------------------------------------------
// 5) approx top-16 candidates per batch (ties -> lower index)
// ---------------------------------------------------------------
__global__ void topk_cand_kernel() {
    __shared__ float sv[S_];
    __shared__ float rv[256];
    __shared__ int   ri[256];
    int b = blockIdx.x, tid = threadIdx.x;
    for (int i = tid; i < S_; i += 256) sv[i] = g_score[(size_t)b * S_ + i];
    __syncthreads();
    for (int k = 0; k < NCAND; k++) {
        float best = -INFINITY; int bi = S_;
        for (int i = tid; i < S_; i += 256) {
            float v = sv[i];
            if (v > best || (v == best && i < bi)) { best = v; bi = i; }
        }
        rv[tid] = best; ri[tid] = bi;
        __syncthreads();
        for (int off = 128; off > 0; off >>= 1) {
            if (tid < off) {
                float v2 = rv[tid + off]; int i2 = ri[tid + off];
                if (v2 > rv[tid] || (v2 == rv[tid] && i2 < ri[tid])) {
                    rv[tid] = v2; ri[tid] = i2;
                }
            }
            __syncthreads();
        }
        if (tid == 0) { g_cand[b * NCAND + k] = ri[0]; sv[ri[0]] = -INFINITY; }
        __syncthreads();
    }
}

// ---------------------------------------------------------------
// 6) exact fp32 rescore of 16 candidates (grid: (half, b))
// ---------------------------------------------------------------
__global__ __launch_bounds__(256) void rescore_kernel(
    const float* __restrict__ x, const float* __restrict__ W2)
{
    __shared__ float xcol[NCAND][D_];
    __shared__ int   scand[NCAND];
    __shared__ float wsum[8][NCAND];
    int h = blockIdx.x, b = blockIdx.y;
    int tid = threadIdx.x, lane = tid & 31, wid = tid >> 5;

    if (tid < NCAND) scand[tid] = g_cand[b * NCAND + tid];
    __syncthreads();
    for (int idx = tid; idx < NCAND * D_; idx += 256) {
        int c = idx >> 9, e = idx & 511;
        xcol[c][e] = x[((size_t)b * D_ + e) * S_ + scand[c]];
    }
    __syncthreads();

    int d = h * 256 + tid;
    float accv[NCAND];
    #pragma unroll
    for (int c = 0; c < NCAND; c++) accv[c] = 0.f;
    const float* wt = g_w1t + d;
    for (int e = 0; e < D_; e++) {
        float wv = wt[(size_t)e * D_];
        #pragma unroll
        for (int c = 0; c < NCAND; c++)
            accv[c] = fmaf(wv, xcol[c][e], accv[c]);
    }
    float w2v = W2[d];
    float gv  = g_gb[b * D_ + d];
    #pragma unroll
    for (int c = 0; c < NCAND; c++) {
        float hv = accv[c] + g_p1[(size_t)scand[c] * D_ + d] + gv;
        hv = fmaxf(hv, 0.f);
        float part = hv * w2v;
        #pragma unroll
        for (int off = 16; off > 0; off >>= 1)
            part += __shfl_xor_sync(0xffffffffu, part, off);
        if (lane == 0) wsum[wid][c] = part;
    }
    __syncthreads();
    if (tid < NCAND) {
        float s = 0.f;
        #pragma unroll
        for (int q = 0; q < 8; q++) s += wsum[q][tid];
        g_cs[(b * 2 + h) * NCAND + tid] = s;
    }
}

// ---------------------------------------------------------------
// 7) final exact top-8 + ascending sort
// ---------------------------------------------------------------
__global__ void final_select_kernel() {
    int b = blockIdx.x;
    if (threadIdx.x != 0) return;
    float sc[NCAND];
    int   id[NCAND];
    bool  used[NCAND];
    for (int c = 0; c < NCAND; c++) {
        sc[c] = g_cs[(b * 2) * NCAND + c] + g_cs[(b * 2 + 1) * NCAND + c];
        id[c] = g_cand[b * NCAND + c];
        used[c] = false;
    }
    int chosen[K_];
    for (int k = 0; k < K_; k++) {
        float best = -INFINITY; int bi = S_, bc = -1;
        for (int c = 0; c < NCAND; c++) {
            if (used[c]) continue;
            if (sc[c] > best || (sc[c] == best && id[c] < bi)) {
                best = sc[c]; bi = id[c]; bc = c;
            }
        }
        used[bc] = true;
        chosen[k] = bi;
    }
    for (int a = 1; a < K_; a++) {
        int v = chosen[a]; int j = a - 1;
        while (j >= 0 && chosen[j] > v) { chosen[j + 1] = chosen[j]; j--; }
        chosen[j + 1] = v;
    }
    for (int k = 0; k < K_; k++) g_idx[b * K_ + k] = chosen[k];
}

// ---------------------------------------------------------------
// 8) outputs
// ---------------------------------------------------------------
__global__ void zero_indices_kernel(float* __restrict__ out) {
    size_t i = (size_t)blockIdx.x * blockDim.x + threadIdx.x;
    ((float4*)out)[i] = make_float4(0.f, 0.f, 0.f, 0.f);
}
__global__ void scatter_ones_kernel(float* __restrict__ out) {
    int t = threadIdx.x;
    if (t < B_ * K_) out[(size_t)t * S_ + g_idx[t]] = 1.0f;
}
__global__ void gather_selected_kernel(const float* __restrict__ x,
                                       float* __restrict__ out) {
    int bk = blockIdx.x;
    int b = bk / K_;
    int s = g_idx[bk];
    int d = threadIdx.x;
    out[(size_t)bk * D_ + d] = x[(size_t)b * D_ * S_ + (size_t)d * S_ + s];
}

// ---------------------------------------------------------------
extern "C" void kernel_launch(void* const* d_in, const int* in_sizes, int n_in,
                              void* d_out, int out_size) {
    const float* x  = (const float*)d_in[0];
    const float* W1 = (const float*)d_in[1];
    const float* b1 = (const float*)d_in[2];
    const float* W2 = (const float*)d_in[3];
    const float* b2 = (const float*)d_in[4];
    float* out = (float*)d_out;

    const size_t IDX_SZ = (size_t)B_ * K_ * S_;
    const size_t SEL_SZ = (size_t)B_ * K_ * D_;
    float* out_idx  = out;
    float* out_sel  = out + IDX_SZ;
    float* out_feat = out + IDX_SZ + SEL_SZ;

    cudaFuncSetAttribute(fused_mma_kernel,
                         cudaFuncAttributeMaxDynamicSharedMemorySize, SMEM_DYN);
    cudaFuncSetAttribute(p1_mma_kernel,
                         cudaFuncAttributeMaxDynamicSharedMemorySize, P1_SMEM);

    transpose_fused_kernel<<<dim3(S_ / 64, D_ / 64, B_), 256>>>(x, out_feat); // 1
    pew1_meang_kernel<<<S_ + (D_ * TWO_D) / 512 + B_, 512>>>(W1);             // 2
    p1_mma_kernel<<<dim3(S_ / 128, D_ / 128), 256, P1_SMEM>>>(b1);            // 3
    fused_mma_kernel<<<dim3(S_ / 128, B_), 256, SMEM_DYN>>>(x, W2, b2);       // 4 (profiled)
    topk_cand_kernel<<<B_, 256>>>();                                          // 5
    rescore_kernel<<<dim3(2, B_), 256>>>(x, W2);                              // 6
    final_select_kernel<<<B_, 32>>>();                                        // 7
    zero_indices_kernel<<<(unsigned)(IDX_SZ / 4 / 256), 256>>>(out_idx);      // 8
    scatter_ones_kernel<<<1, 512>>>(out_idx);                                 // 9
    gather_selected_kernel<<<B_ * K_, 512>>>(x, out_sel);                     // 10
}